// round 1
// baseline (speedup 1.0000x reference)
#include <cuda_runtime.h>

// Problem shape (fixed for this problem instance)
#define BB 4096
#define GG 100
#define TT 24
#define NB 8   // b-rows per block -> blockDim = (24, 8) = 192 threads

// Sorted merit order + sorted prices for [0]=up, [1]=dn directions.
// Entry value GG means "slack" (load shed / spill).
__device__ int   g_order[2][GG + 1];
__device__ float g_price[2][GG + 1];

// ---------------------------------------------------------------------------
// Setup: stable argsort of the 101 prices per direction (O(n^2), one block).
// Reference: prices_all = concat(ratio*b_G, slack_price); order = argsort.
// jnp.argsort is stable -> tie-break by original index.
// ---------------------------------------------------------------------------
__global__ void setup_kernel(const float* __restrict__ b_G,
                             const float* __restrict__ voll,
                             const float* __restrict__ vosp,
                             const float* __restrict__ rt_up_ratio,
                             const float* __restrict__ rt_dn_ratio) {
    __shared__ float p[2][GG + 1];
    int i = threadIdx.x;
    if (i <= GG) {
        float bg = (i < GG) ? b_G[i] : 0.0f;
        p[0][i] = (i < GG) ? (*rt_up_ratio) * bg : *voll;
        p[1][i] = (i < GG) ? (*rt_dn_ratio) * bg : *vosp;
    }
    __syncthreads();
    if (i <= GG) {
        #pragma unroll
        for (int dir = 0; dir < 2; ++dir) {
            float pi = p[dir][i];
            int rank = 0;
            for (int j = 0; j <= GG; ++j) {
                float pj = p[dir][j];
                rank += (pj < pi) || (pj == pi && j < i);
            }
            g_order[dir][rank] = i;
            g_price[dir][rank] = pi;
        }
    }
}

// ---------------------------------------------------------------------------
// Main: one thread per (b,t). Greedy merit-order scan over 101 sorted entries,
// up and dn fused in one loop for memory-level parallelism.
// ---------------------------------------------------------------------------
__global__ __launch_bounds__(24 * NB)
void dispatch_kernel(const float* __restrict__ R_up,
                     const float* __restrict__ R_dn,
                     const float* __restrict__ omega,
                     float* __restrict__ du,
                     float* __restrict__ dd,
                     float* __restrict__ LS,
                     float* __restrict__ SP,
                     float* __restrict__ rt_obj) {
    __shared__ int   s_ord_u[GG + 1];
    __shared__ float s_pr_u [GG + 1];
    __shared__ int   s_ord_d[GG + 1];
    __shared__ float s_pr_d [GG + 1];
    __shared__ float s_cost[NB][TT];

    const int tx  = threadIdx.x;           // t
    const int ty  = threadIdx.y;           // local b
    const int tid = ty * TT + tx;

    for (int k = tid; k <= GG; k += TT * NB) {
        s_ord_u[k] = g_order[0][k];
        s_pr_u [k] = g_price[0][k];
        s_ord_d[k] = g_order[1][k];
        s_pr_d [k] = g_price[1][k];
    }
    __syncthreads();

    const int b  = blockIdx.x * NB + ty;
    const int bt = b * TT + tx;
    const int base = b * (GG * TT) + tx;

    const float w = omega[bt];
    float rem_u = fmaxf(w, 0.0f);
    float rem_d = fmaxf(-w, 0.0f);
    float cost  = 0.0f;

    const float* __restrict__ Ru = R_up + base;
    const float* __restrict__ Rd = R_dn + base;
    float* __restrict__ Du = du + base;
    float* __restrict__ Dd = dd + base;

    #pragma unroll 4
    for (int gi = 0; gi <= GG; ++gi) {
        // --- up direction ---
        {
            int   g = s_ord_u[gi];
            float p = s_pr_u[gi];
            if (g < GG) {
                float cap = Ru[g * TT];
                float a = fminf(rem_u, cap);
                rem_u -= a;
                Du[g * TT] = a;
                cost = fmaf(p, a, cost);
            } else {
                LS[bt] = rem_u;
                cost = fmaf(p, rem_u, cost);
                rem_u = 0.0f;
            }
        }
        // --- dn direction ---
        {
            int   g = s_ord_d[gi];
            float p = s_pr_d[gi];
            if (g < GG) {
                float cap = Rd[g * TT];
                float a = fminf(rem_d, cap);
                rem_d -= a;
                Dd[g * TT] = a;
                cost = fmaf(p, a, cost);
            } else {
                SP[bt] = rem_d;
                cost = fmaf(p, rem_d, cost);
                rem_d = 0.0f;
            }
        }
    }

    // Deterministic per-b reduction of cost over the 24 t's.
    s_cost[ty][tx] = cost;
    __syncthreads();
    if (tx == 0) {
        float s = 0.0f;
        #pragma unroll
        for (int t = 0; t < TT; ++t) s += s_cost[ty][t];
        rt_obj[b] = s;
    }
}

extern "C" void kernel_launch(void* const* d_in, const int* in_sizes, int n_in,
                              void* d_out, int out_size) {
    const float* R_up        = (const float*)d_in[0];
    const float* R_dn        = (const float*)d_in[1];
    const float* omega_true  = (const float*)d_in[2];
    const float* b_G         = (const float*)d_in[3];
    const float* voll        = (const float*)d_in[4];
    const float* vosp        = (const float*)d_in[5];
    const float* rt_up_ratio = (const float*)d_in[6];
    const float* rt_dn_ratio = (const float*)d_in[7];

    float* out = (float*)d_out;
    float* du  = out;
    float* dd  = du + (size_t)BB * GG * TT;
    float* LS  = dd + (size_t)BB * GG * TT;
    float* SP  = LS + (size_t)BB * TT;
    float* rt  = SP + (size_t)BB * TT;

    setup_kernel<<<1, 128>>>(b_G, voll, vosp, rt_up_ratio, rt_dn_ratio);

    dim3 block(TT, NB);
    dim3 grid(BB / NB);
    dispatch_kernel<<<grid, block>>>(R_up, R_dn, omega_true, du, dd, LS, SP, rt);
}

// round 2
// speedup vs baseline: 1.5057x; 1.5057x over previous
#include <cuda_runtime.h>

// Problem shape (fixed)
#define BB 4096
#define GG 100
#define TT 24
#define NCH 8          // chunk-threads per (b,t)
#define CH 13          // entries per chunk: 8*13 = 104 >= 101
#define PADN (NCH*CH)  // 104
#define NB3 2          // b's per block -> blockDim (24,8,2) = 384

// Sorted merit order + prices, padded to 104. order: 0..GG-1 = generator,
// GG = slack, -1 = pad (cap 0). [0]=up, [1]=dn.
__device__ int   g_order[2][PADN];
__device__ float g_price[2][PADN];

// ---------------------------------------------------------------------------
// Setup: stable argsort of 101 prices per direction (O(n^2), one block).
// ---------------------------------------------------------------------------
__global__ void setup_kernel(const float* __restrict__ b_G,
                             const float* __restrict__ voll,
                             const float* __restrict__ vosp,
                             const float* __restrict__ rt_up_ratio,
                             const float* __restrict__ rt_dn_ratio) {
    __shared__ float p[2][GG + 1];
    int i = threadIdx.x;
    if (i <= GG) {
        float bg = (i < GG) ? b_G[i] : 0.0f;
        p[0][i] = (i < GG) ? (*rt_up_ratio) * bg : *voll;
        p[1][i] = (i < GG) ? (*rt_dn_ratio) * bg : *vosp;
    }
    __syncthreads();
    if (i <= GG) {
        #pragma unroll
        for (int dir = 0; dir < 2; ++dir) {
            float pi = p[dir][i];
            int rank = 0;
            for (int j = 0; j <= GG; ++j) {
                float pj = p[dir][j];
                rank += (pj < pi) || (pj == pi && j < i);
            }
            g_order[dir][rank] = i;
            g_price[dir][rank] = pi;
        }
    } else if (i < PADN + (PADN - (GG + 1))) {
        // pad entries 101..103 for both directions
        int k = i - (GG + 1);            // 0..2 (threads 101..103)
        if (k < PADN - (GG + 1)) {
            g_order[0][GG + 1 + k] = -1;  g_price[0][GG + 1 + k] = 0.0f;
            g_order[1][GG + 1 + k] = -1;  g_price[1][GG + 1 + k] = 0.0f;
        }
    }
}

// ---------------------------------------------------------------------------
// Main: 8 chunk-threads per (b,t). Parallel prefix-sum reformulation of the
// greedy dispatch: alloc_i = clip(dem - before_i, 0, cap_i).
// ---------------------------------------------------------------------------
__global__ __launch_bounds__(TT * NCH * NB3)
void dispatch_kernel(const float* __restrict__ R_up,
                     const float* __restrict__ R_dn,
                     const float* __restrict__ omega,
                     float* __restrict__ du,
                     float* __restrict__ dd,
                     float* __restrict__ LS,
                     float* __restrict__ SP,
                     float* __restrict__ rt_obj) {
    __shared__ int   s_ord[2][PADN];
    __shared__ float s_pr [2][PADN];
    __shared__ float s_sum[2][NB3][NCH][TT];
    __shared__ float s_cost[NB3][NCH][TT];

    const int tx = threadIdx.x;   // t
    const int ty = threadIdx.y;   // chunk
    const int tz = threadIdx.z;   // local b
    const int tid = tx + TT * (ty + NCH * tz);

    if (tid < PADN) {
        s_ord[0][tid] = g_order[0][tid];  s_pr[0][tid] = g_price[0][tid];
        s_ord[1][tid] = g_order[1][tid];  s_pr[1][tid] = g_price[1][tid];
    }
    __syncthreads();

    const int b    = blockIdx.x * NB3 + tz;
    const int bt   = b * TT + tx;
    const int base = b * (GG * TT) + tx;

    const float w     = omega[bt];
    const float dem_u = fmaxf(w, 0.0f);
    const float dem_d = fmaxf(-w, 0.0f);

    const float* __restrict__ Ru = R_up + base;
    const float* __restrict__ Rd = R_dn + base;
    float* __restrict__ Du = du + base;
    float* __restrict__ Dd = dd + base;

    const int gi0 = ty * CH;

    // Phase 1: load chunk caps into registers (max MLP), local sums.
    float cu[CH], cd[CH];
    float su = 0.0f, sd = 0.0f;
    #pragma unroll
    for (int i = 0; i < CH; ++i) {
        int gu = s_ord[0][gi0 + i];
        float c;
        if (gu >= 0 && gu < GG)      c = __ldg(&Ru[gu * TT]);
        else if (gu == GG)           c = dem_u;
        else                         c = 0.0f;
        cu[i] = c;  su += c;

        int gd = s_ord[1][gi0 + i];
        if (gd >= 0 && gd < GG)      c = __ldg(&Rd[gd * TT]);
        else if (gd == GG)           c = dem_d;
        else                         c = 0.0f;
        cd[i] = c;  sd += c;
    }

    s_sum[0][tz][ty][tx] = su;
    s_sum[1][tz][ty][tx] = sd;
    __syncthreads();

    // Exclusive prefix over chunk sums (ascending chunk = ascending rank).
    float bu = 0.0f, bd = 0.0f;
    #pragma unroll
    for (int c = 0; c < NCH; ++c) {
        if (c < ty) {
            bu += s_sum[0][tz][c][tx];
            bd += s_sum[1][tz][c][tx];
        }
    }

    // Phase 2: alloc = clip(dem - before, 0, cap); stores + cost.
    float cost  = 0.0f;
    float run_u = bu, run_d = bd;
    #pragma unroll
    for (int i = 0; i < CH; ++i) {
        {
            int   g = s_ord[0][gi0 + i];
            float p = s_pr [0][gi0 + i];
            float a = fminf(fmaxf(dem_u - run_u, 0.0f), cu[i]);
            run_u += cu[i];
            if (g >= 0) {
                cost = fmaf(p, a, cost);
                if (g < GG) Du[g * TT] = a;
                else        LS[bt]     = a;
            }
        }
        {
            int   g = s_ord[1][gi0 + i];
            float p = s_pr [1][gi0 + i];
            float a = fminf(fmaxf(dem_d - run_d, 0.0f), cd[i]);
            run_d += cd[i];
            if (g >= 0) {
                cost = fmaf(p, a, cost);
                if (g < GG) Dd[g * TT] = a;
                else        SP[bt]     = a;
            }
        }
    }

    // Deterministic cost reduction: chunks first, then t, per b.
    s_cost[tz][ty][tx] = cost;
    __syncthreads();
    if (ty == 0) {
        float s = 0.0f;
        #pragma unroll
        for (int c = 0; c < NCH; ++c) s += s_cost[tz][c][tx];
        s_cost[tz][0][tx] = s;
    }
    __syncthreads();
    if (ty == 0 && tx == 0) {
        float s = 0.0f;
        #pragma unroll
        for (int t = 0; t < TT; ++t) s += s_cost[tz][0][t];
        rt_obj[b] = s;
    }
}

extern "C" void kernel_launch(void* const* d_in, const int* in_sizes, int n_in,
                              void* d_out, int out_size) {
    const float* R_up        = (const float*)d_in[0];
    const float* R_dn        = (const float*)d_in[1];
    const float* omega_true  = (const float*)d_in[2];
    const float* b_G         = (const float*)d_in[3];
    const float* voll        = (const float*)d_in[4];
    const float* vosp        = (const float*)d_in[5];
    const float* rt_up_ratio = (const float*)d_in[6];
    const float* rt_dn_ratio = (const float*)d_in[7];

    float* out = (float*)d_out;
    float* du  = out;
    float* dd  = du + (size_t)BB * GG * TT;
    float* LS  = dd + (size_t)BB * GG * TT;
    float* SP  = LS + (size_t)BB * TT;
    float* rt  = SP + (size_t)BB * TT;

    setup_kernel<<<1, 128>>>(b_G, voll, vosp, rt_up_ratio, rt_dn_ratio);

    dim3 block(TT, NCH, NB3);
    dim3 grid(BB / NB3);
    dispatch_kernel<<<grid, block>>>(R_up, R_dn, omega_true, du, dd, LS, SP, rt);
}